// round 15
// baseline (speedup 1.0000x reference)
#include <cuda_runtime.h>
#include <cuda_fp16.h>
#include <cstdint>

#define Bc 2
#define Sc 2048
#define Dc 1024
#define Hc 16
#define DHc 64
#define BSc (Bc*Sc)
#define BHc (Bc*Hc)

// fp16 scratch (allocation-free rule): __device__ globals
__device__ __align__(16) __half g_qin[BSc*Dc];
__device__ __align__(16) __half g_kin[BSc*Dc];
__device__ __align__(16) __half g_vin[BSc*Dc];
__device__ __align__(16) __half g_wq[Dc*Dc];
__device__ __align__(16) __half g_wk[Dc*Dc];
__device__ __align__(16) __half g_wv[Dc*Dc];
__device__ __align__(16) __half g_wo[Dc*Dc];
__device__ __align__(16) __half g_Qp[BSc*Dc];   // pre-scaled by log2e/8
__device__ __align__(16) __half g_Kp[BSc*Dc];
__device__ __align__(16) __half g_Vp[BSc*Dc];
__device__ __align__(16) __half g_AOp[BSc*Dc];
__device__ float g_il[BHc*Sc];
// E^T[bh][k][q] = exp2(S^T) materialized once by colsum (256 MB)
__device__ __align__(16) __half g_ET[(size_t)BHc * Sc * Sc];

// ---------------------------------------------------------------------------
// Primitives (sm_75+/sm_80+ baseline ISA — family-portable)
// ---------------------------------------------------------------------------
__device__ __forceinline__ uint32_t smem_u32(const void* p) {
    uint32_t a;
    asm("{ .reg .u64 t; cvta.to.shared.u64 t, %1; cvt.u32.u64 %0, t; }"
        : "=r"(a) : "l"(p));
    return a;
}
__device__ __forceinline__ uint32_t pk(float x, float y) {
    __half2 h = __floats2half2_rn(x, y);
    return *(uint32_t*)&h;
}
__device__ __forceinline__ uint32_t ex2h2(uint32_t h2) {
    uint32_t r;
    asm("ex2.approx.f16x2 %0, %1;" : "=r"(r) : "r"(h2));
    return r;
}
__device__ __forceinline__ uint32_t mulh2(uint32_t a, uint32_t b) {
    uint32_t r;
    asm("mul.rn.f16x2 %0, %1, %2;" : "=r"(r) : "r"(a), "r"(b));
    return r;
}
__device__ __forceinline__ void cpa16(uint32_t s, const void* g) {
    asm volatile("cp.async.cg.shared.global [%0], [%1], 16;" :: "r"(s), "l"(g) : "memory");
}
#define CP_COMMIT() asm volatile("cp.async.commit_group;" ::: "memory")
template<int N> __device__ __forceinline__ void cp_wait() {
    asm volatile("cp.async.wait_group %0;" :: "n"(N) : "memory");
}
__device__ __forceinline__ void ldm_x4(uint32_t* r, uint32_t addr) {
    asm volatile("ldmatrix.sync.aligned.m8n8.x4.shared.b16 {%0,%1,%2,%3}, [%4];"
        : "=r"(r[0]), "=r"(r[1]), "=r"(r[2]), "=r"(r[3]) : "r"(addr));
}
__device__ __forceinline__ void ldm_x4t(uint32_t* r, uint32_t addr) {
    asm volatile("ldmatrix.sync.aligned.m8n8.x4.trans.shared.b16 {%0,%1,%2,%3}, [%4];"
        : "=r"(r[0]), "=r"(r[1]), "=r"(r[2]), "=r"(r[3]) : "r"(addr));
}
__device__ __forceinline__ void mma16(float* c,
    uint32_t a0, uint32_t a1, uint32_t a2, uint32_t a3, uint32_t b0, uint32_t b1)
{
    asm("mma.sync.aligned.m16n8k16.row.col.f32.f16.f16.f32 "
        "{%0,%1,%2,%3},{%4,%5,%6,%7},{%8,%9},{%0,%1,%2,%3};"
        : "+f"(c[0]), "+f"(c[1]), "+f"(c[2]), "+f"(c[3])
        : "r"(a0), "r"(a1), "r"(a2), "r"(a3), "r"(b0), "r"(b1));
}
#define ONE2 0x3C003C00u   // fp16x2 {1.0, 1.0}

// ===========================================================================
// Fused fp32 -> fp16 converts: 3 big inputs + 4 weights, one launch
// ===========================================================================
__device__ __forceinline__ void cv8(const float* s, __half* d, size_t i) {
    const float4* sp = (const float4*)s + 2 * i;
    float4 a = sp[0], b = sp[1];
    *(uint4*)(d + 8 * i) =
        make_uint4(pk(a.x, a.y), pk(a.z, a.w), pk(b.x, b.y), pk(b.z, b.w));
}
__global__ __launch_bounds__(256) void conv_all(
    const float* __restrict__ s0, const float* __restrict__ s1,
    const float* __restrict__ s2, const float* __restrict__ w0,
    const float* __restrict__ w1, const float* __restrict__ w2,
    const float* __restrict__ w3,
    __half* __restrict__ d0, __half* __restrict__ d1, __half* __restrict__ d2,
    __half* __restrict__ e0, __half* __restrict__ e1, __half* __restrict__ e2,
    __half* __restrict__ e3, int n8big, int n8w)
{
    size_t i = blockIdx.x * 256 + threadIdx.x;
    if (i < (size_t)n8big) { cv8(s0, d0, i); cv8(s1, d1, i); cv8(s2, d2, i); }
    if (i < (size_t)n8w) { cv8(w0, e0, i); cv8(w1, e1, i); cv8(w2, e2, i); cv8(w3, e3, i); }
}

// ===========================================================================
// Projection GEMM body: C[m,n] = (sum_k A[m,k]W[n,k] + b)*osc
// CTA 128x128, 8 warps (2m x 4n), BK=32, 3-stage cp.async ring.
// ===========================================================================
#define PST 40
#define PROJ_SMEM (6 * 128 * PST * 2)   // 61440 bytes

struct PArgs {
    const __half* A; const __half* W; const float* bias;
    __half* Ch; float* Cf; float osc;
};

__device__ __forceinline__ void proj_issue(
    uint32_t as_b, uint32_t ws_b, const __half* A, const __half* W, int tid, int k0)
{
#pragma unroll
    for (int i = 0; i < 2; i++) {
        int slot = tid + i * 256, row = slot >> 2, ch = slot & 3;
        cpa16(as_b + row * (PST * 2) + ch * 16, A + (size_t)row * Dc + k0 + ch * 8);
        cpa16(ws_b + row * (PST * 2) + ch * 16, W + (size_t)row * Dc + k0 + ch * 8);
    }
}

__device__ void proj_body(const PArgs& p, int bx, int by, __half* psm)
{
    __shared__ float bias_sh[128];

    const int tid = threadIdx.x;
    const int w = tid >> 5, lane = tid & 31;
    const int gr = lane >> 2, tc = lane & 3;
    const int wm = w >> 2, wn = w & 3;
    const int br = by * 128, bc = bx * 128;
    const int l16 = lane & 15, lh = (lane >> 4) << 4;

    const __half* Ab = p.A + (size_t)br * Dc;
    const __half* Wb = p.W + (size_t)bc * Dc;
    const uint32_t base = smem_u32(psm);
    if (tid < 128) bias_sh[tid] = p.bias[bc + tid];

    float acc[4][4][4];
#pragma unroll
    for (int i = 0; i < 4; i++)
#pragma unroll
        for (int j = 0; j < 4; j++)
#pragma unroll
            for (int k = 0; k < 4; k++) acc[i][j][k] = 0.f;

    proj_issue(base, base + 30720u, Ab, Wb, tid, 0);  CP_COMMIT();
    proj_issue(base + 10240u, base + 40960u, Ab, Wb, tid, 32);  CP_COMMIT();

    for (int it = 0; it < 32; it++) {
        cp_wait<1>();
        __syncthreads();
        if (it + 2 < 32) {
            int s = (it + 2) % 3;
            proj_issue(base + (uint32_t)s * 10240u, base + 30720u + (uint32_t)s * 10240u,
                       Ab, Wb, tid, (it + 2) * 32);
        }
        CP_COMMIT();

        const int s = it % 3;
        const uint32_t as_b = base + (uint32_t)s * 10240u;
        const __half* Ws_s = psm + 15360 + s * 5120;
#pragma unroll
        for (int kk = 0; kk < 2; kk++) {
            uint32_t af[4][4], bf[4][2];
#pragma unroll
            for (int mi = 0; mi < 4; mi++)
                ldm_x4(af[mi], as_b + (uint32_t)(wm * 64 + mi * 16 + l16) * (PST * 2)
                                    + kk * 32 + lh);
#pragma unroll
            for (int ni = 0; ni < 4; ni++) {
                int hidx = (wn * 32 + ni * 8 + gr) * PST + kk * 16 + 2 * tc;
                bf[ni][0] = *(const uint32_t*)&Ws_s[hidx];
                bf[ni][1] = *(const uint32_t*)&Ws_s[hidx + 8];
            }
#pragma unroll
            for (int mi = 0; mi < 4; mi++)
#pragma unroll
                for (int ni = 0; ni < 4; ni++)
                    mma16(acc[mi][ni], af[mi][0], af[mi][1], af[mi][2], af[mi][3],
                          bf[ni][0], bf[ni][1]);
        }
    }

#pragma unroll
    for (int mi = 0; mi < 4; mi++) {
        int m0 = br + wm * 64 + mi * 16 + gr;
#pragma unroll
        for (int ni = 0; ni < 4; ni++) {
            int n = wn * 32 + ni * 8 + 2 * tc;
            float v00 = (acc[mi][ni][0] + bias_sh[n]) * p.osc;
            float v01 = (acc[mi][ni][1] + bias_sh[n + 1]) * p.osc;
            float v10 = (acc[mi][ni][2] + bias_sh[n]) * p.osc;
            float v11 = (acc[mi][ni][3] + bias_sh[n + 1]) * p.osc;
            if (p.Cf) {
                *(float2*)(p.Cf + (size_t)m0 * Dc + bc + n) = make_float2(v00, v01);
                *(float2*)(p.Cf + (size_t)(m0 + 8) * Dc + bc + n) = make_float2(v10, v11);
            } else {
                *(uint32_t*)(p.Ch + (size_t)m0 * Dc + bc + n) = pk(v00, v01);
                *(uint32_t*)(p.Ch + (size_t)(m0 + 8) * Dc + bc + n) = pk(v10, v11);
            }
        }
    }
}

__global__ __launch_bounds__(256, 2) void proj_mma(PArgs p0, PArgs p1, PArgs p2)
{
    extern __shared__ __half psm[];
    const PArgs p = (blockIdx.z == 0) ? p0 : (blockIdx.z == 1) ? p1 : p2;
    proj_body(p, blockIdx.x, blockIdx.y, psm);
}

// ===========================================================================
// Column softmax body: il[bh,k] = 1/sum_q exp2(Qs·K), AND materializes
// E^T[k][q] = exp2(S^T) to g_ET (fp16). S^T = K·Q^T; L via ones-MMA.
// ===========================================================================
#define AST 72
#define CS_SMEM (3 * 128 * AST * 2)   // 55296 bytes

__device__ void colsum_body(int bh, int kb4, __half* csm)
{
    __shared__ float Lsh[2][128];

    const int tid = threadIdx.x;
    const int w = tid >> 5, lane = tid & 31;
    const int gr = lane >> 2, tc = lane & 3;
    const int wm = w >> 1, wn = w & 1;
    const int b = bh >> 4, h = bh & 15;
    const int kb = kb4 * 128;
    const int l16 = lane & 15, lh = (lane >> 4) << 4;

    const uint32_t ks_b = smem_u32(csm);
    const uint32_t qs_bb[2] = { ks_b + 128u * AST * 2u, ks_b + 2u * 128u * AST * 2u };

    const __half* Kbase = g_Kp + (size_t)(b * Sc + kb) * Dc + h * DHc;
    const __half* Qbase = g_Qp + (size_t)(b * Sc) * Dc + h * DHc;
    // E^T store base for this warp's k rows (mi=0); mi adds 16 rows
    __half* etw = g_ET + ((size_t)bh * Sc + kb + wm * 32 + gr) * Sc
                + wn * 64 + 2 * tc;

#pragma unroll
    for (int i = 0; i < 4; i++) {
        int slot = tid + i * 256, row = slot >> 3, ch = slot & 7;
        cpa16(ks_b + row * (AST * 2) + ch * 16, Kbase + (size_t)row * Dc + ch * 8);
        cpa16(qs_bb[0] + row * (AST * 2) + ch * 16, Qbase + (size_t)row * Dc + ch * 8);
    }
    CP_COMMIT();

    float La[2][4];
#pragma unroll
    for (int mi = 0; mi < 2; mi++)
#pragma unroll
        for (int k = 0; k < 4; k++) La[mi][k] = 0.f;

    for (int qt = 0; qt < 16; qt++) {
        cp_wait<0>();
        __syncthreads();
        if (qt + 1 < 16) {
            const __half* Qn = Qbase + (size_t)(qt + 1) * 128 * Dc;
            const uint32_t dstb = qs_bb[(qt + 1) & 1];
#pragma unroll
            for (int i = 0; i < 4; i++) {
                int slot = tid + i * 256, row = slot >> 3, ch = slot & 7;
                cpa16(dstb + row * (AST * 2) + ch * 16, Qn + (size_t)row * Dc + ch * 8);
            }
        }
        CP_COMMIT();

        const __half* Qs = (const __half*)(csm + (qt & 1 ? 2 : 1) * 128 * AST);
        float sv[2][8][4];
#pragma unroll
        for (int mi = 0; mi < 2; mi++)
#pragma unroll
            for (int ni = 0; ni < 8; ni++)
#pragma unroll
                for (int k = 0; k < 4; k++) sv[mi][ni][k] = 0.f;

#pragma unroll
        for (int st = 0; st < 4; st++) {
            uint32_t af[2][4], bf[8][2];
#pragma unroll
            for (int mi = 0; mi < 2; mi++)
                ldm_x4(af[mi], ks_b + (uint32_t)(wm * 32 + mi * 16 + l16) * (AST * 2)
                                    + st * 32 + lh);
#pragma unroll
            for (int ni = 0; ni < 8; ni++) {
                int hidx = (wn * 64 + ni * 8 + gr) * AST + st * 16 + 2 * tc;
                bf[ni][0] = *(const uint32_t*)&Qs[hidx];
                bf[ni][1] = *(const uint32_t*)&Qs[hidx + 8];
            }
#pragma unroll
            for (int mi = 0; mi < 2; mi++)
#pragma unroll
                for (int ni = 0; ni < 8; ni++)
                    mma16(sv[mi][ni], af[mi][0], af[mi][1], af[mi][2], af[mi][3],
                          bf[ni][0], bf[ni][1]);
        }

        // E = exp2(S^T) fp16; store E^T[k][q]; L += E · ones
        __half* etq = etw + (size_t)qt * 128;
#pragma unroll
        for (int mi = 0; mi < 2; mi++) {
            __half* etm = etq + (size_t)(mi * 16) * Sc;
#pragma unroll
            for (int ks2 = 0; ks2 < 4; ks2++) {
                const float* s0 = sv[mi][2 * ks2];
                const float* s1 = sv[mi][2 * ks2 + 1];
                uint32_t a0 = ex2h2(pk(s0[0], s0[1]));   // (k=gr,   q=2tc)
                uint32_t a1 = ex2h2(pk(s0[2], s0[3]));   // (k=gr+8, q=2tc)
                uint32_t a2 = ex2h2(pk(s1[0], s1[1]));   // (k=gr,   q=2tc+8)
                uint32_t a3 = ex2h2(pk(s1[2], s1[3]));   // (k=gr+8, q=2tc+8)
                __half* etk = etm + ks2 * 16;
                *(uint32_t*)etk = a0;
                *(uint32_t*)(etk + 8 * Sc) = a1;
                *(uint32_t*)(etk + 8) = a2;
                *(uint32_t*)(etk + 8 * Sc + 8) = a3;
                mma16(La[mi], a0, a1, a2, a3, ONE2, ONE2);
            }
        }
    }

    if (tc == 0) {
#pragma unroll
        for (int mi = 0; mi < 2; mi++) {
            Lsh[wn][wm * 32 + mi * 16 + gr] = La[mi][0];
            Lsh[wn][wm * 32 + mi * 16 + gr + 8] = La[mi][2];
        }
    }
    __syncthreads();
    if (tid < 128) g_il[bh * Sc + kb + tid] = 1.f / (Lsh[0][tid] + Lsh[1][tid]);
}

// ===========================================================================
// Fused V-projection + column-softmax(+E store): one launch, co-scheduled.
// ===========================================================================
#define FUS_SMEM (PROJ_SMEM > CS_SMEM ? PROJ_SMEM : CS_SMEM)

__global__ __launch_bounds__(256, 2) void fused_vcs(PArgs pv)
{
    extern __shared__ __half fsm[];
    const int bid = blockIdx.x;
    if (bid < 256) {
        proj_body(pv, bid & 7, bid >> 3, fsm);
    } else {
        const int id = bid - 256;
        colsum_body(id >> 4, id & 15, fsm);
    }
}

// ===========================================================================
// Attention PV: O[q,:] = sum_k (E[q,k]*il_k) V[k,:] — no QK recompute.
// E^T tiles loaded from g_ET; P A-frags via ldmatrix.x4.trans
// (frag permutation {r0,r2,r1,r3}); V B-frags via x4.trans.
// CTA: 128 q x one head; 8 warps x 16 q rows. 256 thr, 2 CTAs/SM.
// ===========================================================================
#define ETST 136
#define EOFF0 0
#define EOFF1 (128 * ETST)                       // 17408 halfs
#define VOFF0 (2 * 128 * ETST)                   // 34816
#define VOFF1 (2 * 128 * ETST + 128 * AST)       // 44032
#define ILOFF (2 * 128 * ETST + 2 * 128 * AST)   // 53248 halfs
#define ATTN_SMEM (ILOFF * 2 + 512)              // 107008 bytes

__global__ __launch_bounds__(256, 2) void attn_pv()
{
    extern __shared__ __half asm_[];
    uint32_t* ilh = (uint32_t*)(asm_ + ILOFF);   // [2][64] half2-packed il

    const int tid = threadIdx.x;
    const int w = tid >> 5, lane = tid & 31;
    const int gr = lane >> 2, tc = lane & 3;
    const int bh = blockIdx.y, b = bh >> 4, h = bh & 15;
    const int qb = blockIdx.x * 128;
    const int l16 = lane & 15, lh = (lane >> 4) << 4;

    const uint32_t base = smem_u32(asm_);
    const uint32_t es_bb[2] = { base + EOFF0 * 2u, base + EOFF1 * 2u };
    const uint32_t vs_bb[2] = { base + VOFF0 * 2u, base + VOFF1 * 2u };

    const __half* Ebase = g_ET + ((size_t)bh * Sc) * Sc + qb;  // + k*Sc + qcol
    const __half* Vbase = g_Vp + (size_t)(b * Sc) * Dc + h * DHc;

    // prologue: E0 + V0 + il0
#pragma unroll
    for (int i = 0; i < 8; i++) {
        int slot = tid + i * 256, row = slot >> 4, ch = slot & 15;
        cpa16(es_bb[0] + row * (ETST * 2) + ch * 16, Ebase + (size_t)row * Sc + ch * 8);
    }
#pragma unroll
    for (int i = 0; i < 4; i++) {
        int slot = tid + i * 256, row = slot >> 3, ch = slot & 7;
        cpa16(vs_bb[0] + row * (AST * 2) + ch * 16, Vbase + (size_t)row * Dc + ch * 8);
    }
    if (tid < 64)
        ilh[tid] = pk(g_il[bh * Sc + 2 * tid], g_il[bh * Sc + 2 * tid + 1]);
    CP_COMMIT();

    float o[8][4];
#pragma unroll
    for (int ni = 0; ni < 8; ni++)
#pragma unroll
        for (int k = 0; k < 4; k++) o[ni][k] = 0.f;

    for (int kt = 0; kt < 16; kt++) {
        const int buf = kt & 1;
        cp_wait<0>();
        __syncthreads();
        if (kt + 1 < 16) {
            const int nb = (kt + 1) & 1;
            const __half* En = Ebase + (size_t)(kt + 1) * 128 * Sc;
            const __half* Vn = Vbase + (size_t)(kt + 1) * 128 * Dc;
#pragma unroll
            for (int i = 0; i < 8; i++) {
                int slot = tid + i * 256, row = slot >> 4, ch = slot & 15;
                cpa16(es_bb[nb] + row * (ETST * 2) + ch * 16, En + (size_t)row * Sc + ch * 8);
            }
#pragma unroll
            for (int i = 0; i < 4; i++) {
                int slot = tid + i * 256, row = slot >> 3, ch = slot & 7;
                cpa16(vs_bb[nb] + row * (AST * 2) + ch * 16, Vn + (size_t)row * Dc + ch * 8);
            }
            if (tid < 64)
                ilh[nb * 64 + tid] = pk(g_il[bh * Sc + (kt + 1) * 128 + 2 * tid],
                                        g_il[bh * Sc + (kt + 1) * 128 + 2 * tid + 1]);
        }
        CP_COMMIT();

        const uint32_t esb = es_bb[buf];
        const uint32_t vsb = vs_bb[buf];
        const uint32_t* ilbh = ilh + buf * 64;

#pragma unroll
        for (int g = 0; g < 8; g++) {            // 16-k groups
            uint32_t er[4];
            ldm_x4t(er, esb + (uint32_t)(g * 16 + l16) * (ETST * 2)
                            + (uint32_t)(w * 16) * 2 + lh);
            uint32_t il0 = ilbh[g * 8 + tc];
            uint32_t il1 = ilbh[g * 8 + 4 + tc];
            // trans-frag -> A-frag permutation: a0=r0, a1=r2, a2=r1, a3=r3
            uint32_t a0 = mulh2(er[0], il0);
            uint32_t a1 = mulh2(er[2], il0);
            uint32_t a2 = mulh2(er[1], il1);
            uint32_t a3 = mulh2(er[3], il1);

#pragma unroll
            for (int ni2 = 0; ni2 < 4; ni2++) {
                uint32_t bv[4];
                ldm_x4t(bv, vsb + (uint32_t)(g * 16 + l16) * (AST * 2)
                               + (uint32_t)(ni2 * 32) + lh);
                mma16(o[2 * ni2],     a0, a1, a2, a3, bv[0], bv[1]);
                mma16(o[2 * ni2 + 1], a0, a1, a2, a3, bv[2], bv[3]);
            }
        }
    }

    const int q0 = qb + w * 16 + gr;
#pragma unroll
    for (int ni = 0; ni < 8; ni++) {
        int dg = h * DHc + ni * 8 + 2 * tc;
        *(uint32_t*)(g_AOp + (size_t)(b * Sc + q0) * Dc + dg) = pk(o[ni][0], o[ni][1]);
        *(uint32_t*)(g_AOp + (size_t)(b * Sc + q0 + 8) * Dc + dg) = pk(o[ni][2], o[ni][3]);
    }
}

// ===========================================================================
// Host
// ===========================================================================
extern "C" void kernel_launch(void* const* d_in, const int* in_sizes, int n_in,
                              void* d_out, int out_size)
{
    (void)in_sizes; (void)n_in; (void)out_size;
    const float* query = (const float*)d_in[0];
    const float* key   = (const float*)d_in[1];
    const float* value = (const float*)d_in[2];
    const float* Wq = (const float*)d_in[3];
    const float* bq = (const float*)d_in[4];
    const float* Wk = (const float*)d_in[5];
    const float* bk = (const float*)d_in[6];
    const float* Wv = (const float*)d_in[7];
    const float* bv = (const float*)d_in[8];
    const float* Wo = (const float*)d_in[9];
    const float* bo = (const float*)d_in[10];
    float* out = (float*)d_out;

    void *qin, *kin, *vin, *wqp, *wkp, *wvp, *wop, *Qp, *Kp, *Vp, *AOp;
    cudaGetSymbolAddress(&qin, g_qin); cudaGetSymbolAddress(&kin, g_kin);
    cudaGetSymbolAddress(&vin, g_vin); cudaGetSymbolAddress(&wqp, g_wq);
    cudaGetSymbolAddress(&wkp, g_wk);  cudaGetSymbolAddress(&wvp, g_wv);
    cudaGetSymbolAddress(&wop, g_wo);  cudaGetSymbolAddress(&Qp, g_Qp);
    cudaGetSymbolAddress(&Kp, g_Kp);   cudaGetSymbolAddress(&Vp, g_Vp);
    cudaGetSymbolAddress(&AOp, g_AOp);

    cudaFuncSetAttribute(proj_mma,  cudaFuncAttributeMaxDynamicSharedMemorySize, PROJ_SMEM);
    cudaFuncSetAttribute(fused_vcs, cudaFuncAttributeMaxDynamicSharedMemorySize, FUS_SMEM);
    cudaFuncSetAttribute(attn_pv,   cudaFuncAttributeMaxDynamicSharedMemorySize, ATTN_SMEM);

    const int n8big = BSc * Dc / 8, n8w = Dc * Dc / 8;
    conv_all<<<n8big / 256, 256>>>(query, key, value, Wq, Wk, Wv, Wo,
        (__half*)qin, (__half*)kin, (__half*)vin,
        (__half*)wqp, (__half*)wkp, (__half*)wvp, (__half*)wop, n8big, n8w);

    PArgs pq = { (__half*)qin, (__half*)wqp, bq, (__half*)Qp, nullptr, 0.125f * 1.44269504f };
    PArgs pkx = { (__half*)kin, (__half*)wkp, bk, (__half*)Kp, nullptr, 1.f };
    PArgs pv = { (__half*)vin, (__half*)wvp, bv, (__half*)Vp, nullptr, 1.f };
    PArgs po = { (__half*)AOp, (__half*)wop, bo, nullptr, out, 1.f };

    dim3 gqk(Dc / 128, BSc / 128, 2);    // (8, 32, 2): Q and K projections
    dim3 gproj(Dc / 128, BSc / 128, 1);  // (8, 32): O projection
    dim3 gattn(Sc / 128, BHc);           // (16, 32)

    proj_mma<<<gqk, 256, PROJ_SMEM>>>(pq, pkx, pkx);
    fused_vcs<<<768, 256, FUS_SMEM>>>(pv);     // V projection ∥ colsum+E store
    attn_pv<<<gattn, 256, ATTN_SMEM>>>();
    proj_mma<<<gproj, 256, PROJ_SMEM>>>(po, po, po);
}

// round 16
// speedup vs baseline: 1.1711x; 1.1711x over previous
#include <cuda_runtime.h>
#include <cuda_fp16.h>
#include <cstdint>

#define Bc 2
#define Sc 2048
#define Dc 1024
#define Hc 16
#define DHc 64
#define BSc (Bc*Sc)
#define BHc (Bc*Hc)

// fp16 scratch (allocation-free rule): __device__ globals
__device__ __align__(16) __half g_qin[BSc*Dc];
__device__ __align__(16) __half g_kin[BSc*Dc];
__device__ __align__(16) __half g_vin[BSc*Dc];
__device__ __align__(16) __half g_wq[Dc*Dc];
__device__ __align__(16) __half g_wk[Dc*Dc];
__device__ __align__(16) __half g_wv[Dc*Dc];
__device__ __align__(16) __half g_wo[Dc*Dc];
__device__ __align__(16) __half g_Qp[BSc*Dc];   // pre-scaled by log2e/8
__device__ __align__(16) __half g_Kp[BSc*Dc];
__device__ __align__(16) __half g_Vp[BSc*Dc];
__device__ __align__(16) __half g_AOp[BSc*Dc];
__device__ float g_il[BHc*Sc];

// ---------------------------------------------------------------------------
// Primitives (sm_75+/sm_80+/sm_90 baseline ISA — family-portable)
// ---------------------------------------------------------------------------
__device__ __forceinline__ uint32_t smem_u32(const void* p) {
    uint32_t a;
    asm("{ .reg .u64 t; cvta.to.shared.u64 t, %1; cvt.u32.u64 %0, t; }"
        : "=r"(a) : "l"(p));
    return a;
}
__device__ __forceinline__ uint32_t pk(float x, float y) {
    __half2 h = __floats2half2_rn(x, y);
    return *(uint32_t*)&h;
}
__device__ __forceinline__ uint32_t ex2h2(uint32_t h2) {
    uint32_t r;
    asm("ex2.approx.f16x2 %0, %1;" : "=r"(r) : "r"(h2));
    return r;
}
__device__ __forceinline__ uint32_t mulh2(uint32_t a, uint32_t b) {
    uint32_t r;
    asm("mul.rn.f16x2 %0, %1, %2;" : "=r"(r) : "r"(a), "r"(b));
    return r;
}
// PDL controls (baseline sm_90 PTX, family-portable)
__device__ __forceinline__ void gdc_launch() {
    asm volatile("griddepcontrol.launch_dependents;" ::: "memory");
}
__device__ __forceinline__ void gdc_wait() {
    asm volatile("griddepcontrol.wait;" ::: "memory");
}
__device__ __forceinline__ void cpa16(uint32_t s, const void* g) {
    asm volatile("cp.async.cg.shared.global [%0], [%1], 16;" :: "r"(s), "l"(g) : "memory");
}
#define CP_COMMIT() asm volatile("cp.async.commit_group;" ::: "memory")
template<int N> __device__ __forceinline__ void cp_wait() {
    asm volatile("cp.async.wait_group %0;" :: "n"(N) : "memory");
}
__device__ __forceinline__ void ldm_x4(uint32_t* r, uint32_t addr) {
    asm volatile("ldmatrix.sync.aligned.m8n8.x4.shared.b16 {%0,%1,%2,%3}, [%4];"
        : "=r"(r[0]), "=r"(r[1]), "=r"(r[2]), "=r"(r[3]) : "r"(addr));
}
__device__ __forceinline__ void ldm_x4t(uint32_t* r, uint32_t addr) {
    asm volatile("ldmatrix.sync.aligned.m8n8.x4.trans.shared.b16 {%0,%1,%2,%3}, [%4];"
        : "=r"(r[0]), "=r"(r[1]), "=r"(r[2]), "=r"(r[3]) : "r"(addr));
}
__device__ __forceinline__ void mma16(float* c,
    uint32_t a0, uint32_t a1, uint32_t a2, uint32_t a3, uint32_t b0, uint32_t b1)
{
    asm("mma.sync.aligned.m16n8k16.row.col.f32.f16.f16.f32 "
        "{%0,%1,%2,%3},{%4,%5,%6,%7},{%8,%9},{%0,%1,%2,%3};"
        : "+f"(c[0]), "+f"(c[1]), "+f"(c[2]), "+f"(c[3])
        : "r"(a0), "r"(a1), "r"(a2), "r"(a3), "r"(b0), "r"(b1));
}
#define ONE2 0x3C003C00u   // fp16x2 {1.0, 1.0}

// ===========================================================================
// Fused fp32 -> fp16 converts: 3 big inputs + 4 weights, one launch
// ===========================================================================
__device__ __forceinline__ void cv8(const float* s, __half* d, size_t i) {
    const float4* sp = (const float4*)s + 2 * i;
    float4 a = sp[0], b = sp[1];
    *(uint4*)(d + 8 * i) =
        make_uint4(pk(a.x, a.y), pk(a.z, a.w), pk(b.x, b.y), pk(b.z, b.w));
}
__global__ __launch_bounds__(256) void conv_all(
    const float* __restrict__ s0, const float* __restrict__ s1,
    const float* __restrict__ s2, const float* __restrict__ w0,
    const float* __restrict__ w1, const float* __restrict__ w2,
    const float* __restrict__ w3,
    __half* __restrict__ d0, __half* __restrict__ d1, __half* __restrict__ d2,
    __half* __restrict__ e0, __half* __restrict__ e1, __half* __restrict__ e2,
    __half* __restrict__ e3, int n8big, int n8w)
{
    gdc_launch();
    size_t i = blockIdx.x * 256 + threadIdx.x;
    if (i < (size_t)n8big) { cv8(s0, d0, i); cv8(s1, d1, i); cv8(s2, d2, i); }
    if (i < (size_t)n8w) { cv8(w0, e0, i); cv8(w1, e1, i); cv8(w2, e2, i); cv8(w3, e3, i); }
}

// ===========================================================================
// Projection GEMM body: C[m,n] = (sum_k A[m,k]W[n,k] + b)*osc
// CTA 128x128, 8 warps (2m x 4n), BK=32, 3-stage cp.async ring.
// ===========================================================================
#define PST 40
#define PROJ_SMEM (6 * 128 * PST * 2)   // 61440 bytes

struct PArgs {
    const __half* A; const __half* W; const float* bias;
    __half* Ch; float* Cf; float osc;
};

__device__ __forceinline__ void proj_issue(
    uint32_t as_b, uint32_t ws_b, const __half* A, const __half* W, int tid, int k0)
{
#pragma unroll
    for (int i = 0; i < 2; i++) {
        int slot = tid + i * 256, row = slot >> 2, ch = slot & 3;
        cpa16(as_b + row * (PST * 2) + ch * 16, A + (size_t)row * Dc + k0 + ch * 8);
        cpa16(ws_b + row * (PST * 2) + ch * 16, W + (size_t)row * Dc + k0 + ch * 8);
    }
}

__device__ void proj_body(const PArgs& p, int bx, int by, __half* psm)
{
    __shared__ float bias_sh[128];

    const int tid = threadIdx.x;
    const int w = tid >> 5, lane = tid & 31;
    const int gr = lane >> 2, tc = lane & 3;
    const int wm = w >> 2, wn = w & 3;
    const int br = by * 128, bc = bx * 128;
    const int l16 = lane & 15, lh = (lane >> 4) << 4;

    const __half* Ab = p.A + (size_t)br * Dc;
    const __half* Wb = p.W + (size_t)bc * Dc;
    const uint32_t base = smem_u32(psm);
    if (tid < 128) bias_sh[tid] = p.bias[bc + tid];

    float acc[4][4][4];
#pragma unroll
    for (int i = 0; i < 4; i++)
#pragma unroll
        for (int j = 0; j < 4; j++)
#pragma unroll
            for (int k = 0; k < 4; k++) acc[i][j][k] = 0.f;

    proj_issue(base, base + 30720u, Ab, Wb, tid, 0);  CP_COMMIT();
    proj_issue(base + 10240u, base + 40960u, Ab, Wb, tid, 32);  CP_COMMIT();

    for (int it = 0; it < 32; it++) {
        cp_wait<1>();
        __syncthreads();
        if (it + 2 < 32) {
            int s = (it + 2) % 3;
            proj_issue(base + (uint32_t)s * 10240u, base + 30720u + (uint32_t)s * 10240u,
                       Ab, Wb, tid, (it + 2) * 32);
        }
        CP_COMMIT();

        const int s = it % 3;
        const uint32_t as_b = base + (uint32_t)s * 10240u;
        const __half* Ws_s = psm + 15360 + s * 5120;
#pragma unroll
        for (int kk = 0; kk < 2; kk++) {
            uint32_t af[4][4], bf[4][2];
#pragma unroll
            for (int mi = 0; mi < 4; mi++)
                ldm_x4(af[mi], as_b + (uint32_t)(wm * 64 + mi * 16 + l16) * (PST * 2)
                                    + kk * 32 + lh);
#pragma unroll
            for (int ni = 0; ni < 4; ni++) {
                int hidx = (wn * 32 + ni * 8 + gr) * PST + kk * 16 + 2 * tc;
                bf[ni][0] = *(const uint32_t*)&Ws_s[hidx];
                bf[ni][1] = *(const uint32_t*)&Ws_s[hidx + 8];
            }
#pragma unroll
            for (int mi = 0; mi < 4; mi++)
#pragma unroll
                for (int ni = 0; ni < 4; ni++)
                    mma16(acc[mi][ni], af[mi][0], af[mi][1], af[mi][2], af[mi][3],
                          bf[ni][0], bf[ni][1]);
        }
    }

#pragma unroll
    for (int mi = 0; mi < 4; mi++) {
        int m0 = br + wm * 64 + mi * 16 + gr;
#pragma unroll
        for (int ni = 0; ni < 4; ni++) {
            int n = wn * 32 + ni * 8 + 2 * tc;
            float v00 = (acc[mi][ni][0] + bias_sh[n]) * p.osc;
            float v01 = (acc[mi][ni][1] + bias_sh[n + 1]) * p.osc;
            float v10 = (acc[mi][ni][2] + bias_sh[n]) * p.osc;
            float v11 = (acc[mi][ni][3] + bias_sh[n + 1]) * p.osc;
            if (p.Cf) {
                *(float2*)(p.Cf + (size_t)m0 * Dc + bc + n) = make_float2(v00, v01);
                *(float2*)(p.Cf + (size_t)(m0 + 8) * Dc + bc + n) = make_float2(v10, v11);
            } else {
                *(uint32_t*)(p.Ch + (size_t)m0 * Dc + bc + n) = pk(v00, v01);
                *(uint32_t*)(p.Ch + (size_t)(m0 + 8) * Dc + bc + n) = pk(v10, v11);
            }
        }
    }
}

// Used for QK projections (primary of fused_vcs) and as O projection
// (PDL secondary of attn — gdc_wait gates the dependent AOp reads).
__global__ __launch_bounds__(256, 2) void proj_mma(PArgs p0, PArgs p1, PArgs p2)
{
    extern __shared__ __half psm[];
    gdc_launch();          // let dependent grid begin launching
    gdc_wait();            // no-op unless this launch used PDL (proj_o)
    const PArgs p = (blockIdx.z == 0) ? p0 : (blockIdx.z == 1) ? p1 : p2;
    proj_body(p, blockIdx.x, blockIdx.y, psm);
}

// ===========================================================================
// Column softmax body: il[bh,k] = 1/sum_q exp2(Qs·K)
// Transposed S^T = K·Q^T; fp16 exp2 frags reduced over q with ones-MMA.
// ===========================================================================
#define AST 72
#define CS_SMEM (3 * 128 * AST * 2)   // 55296 bytes

__device__ void colsum_body(int bh, int kb4, __half* csm)
{
    __shared__ float Lsh[2][128];

    const int tid = threadIdx.x;
    const int w = tid >> 5, lane = tid & 31;
    const int gr = lane >> 2, tc = lane & 3;
    const int wm = w >> 1, wn = w & 1;
    const int b = bh >> 4, h = bh & 15;
    const int kb = kb4 * 128;
    const int l16 = lane & 15, lh = (lane >> 4) << 4;

    const uint32_t ks_b = smem_u32(csm);
    const uint32_t qs_bb[2] = { ks_b + 128u * AST * 2u, ks_b + 2u * 128u * AST * 2u };

    const __half* Kbase = g_Kp + (size_t)(b * Sc + kb) * Dc + h * DHc;
    const __half* Qbase = g_Qp + (size_t)(b * Sc) * Dc + h * DHc;

#pragma unroll
    for (int i = 0; i < 4; i++) {
        int slot = tid + i * 256, row = slot >> 3, ch = slot & 7;
        cpa16(ks_b + row * (AST * 2) + ch * 16, Kbase + (size_t)row * Dc + ch * 8);
        cpa16(qs_bb[0] + row * (AST * 2) + ch * 16, Qbase + (size_t)row * Dc + ch * 8);
    }
    CP_COMMIT();

    float La[2][4];
#pragma unroll
    for (int mi = 0; mi < 2; mi++)
#pragma unroll
        for (int k = 0; k < 4; k++) La[mi][k] = 0.f;

    for (int qt = 0; qt < 16; qt++) {
        cp_wait<0>();
        __syncthreads();
        if (qt + 1 < 16) {
            const __half* Qn = Qbase + (size_t)(qt + 1) * 128 * Dc;
            const uint32_t dstb = qs_bb[(qt + 1) & 1];
#pragma unroll
            for (int i = 0; i < 4; i++) {
                int slot = tid + i * 256, row = slot >> 3, ch = slot & 7;
                cpa16(dstb + row * (AST * 2) + ch * 16, Qn + (size_t)row * Dc + ch * 8);
            }
        }
        CP_COMMIT();

        const __half* Qs = (const __half*)(csm + (qt & 1 ? 2 : 1) * 128 * AST);
        float sv[2][8][4];
#pragma unroll
        for (int mi = 0; mi < 2; mi++)
#pragma unroll
            for (int ni = 0; ni < 8; ni++)
#pragma unroll
                for (int k = 0; k < 4; k++) sv[mi][ni][k] = 0.f;

#pragma unroll
        for (int st = 0; st < 4; st++) {
            uint32_t af[2][4], bf[8][2];
#pragma unroll
            for (int mi = 0; mi < 2; mi++)
                ldm_x4(af[mi], ks_b + (uint32_t)(wm * 32 + mi * 16 + l16) * (AST * 2)
                                    + st * 32 + lh);
#pragma unroll
            for (int ni = 0; ni < 8; ni++) {
                int hidx = (wn * 64 + ni * 8 + gr) * AST + st * 16 + 2 * tc;
                bf[ni][0] = *(const uint32_t*)&Qs[hidx];
                bf[ni][1] = *(const uint32_t*)&Qs[hidx + 8];
            }
#pragma unroll
            for (int mi = 0; mi < 2; mi++)
#pragma unroll
                for (int ni = 0; ni < 8; ni++)
                    mma16(sv[mi][ni], af[mi][0], af[mi][1], af[mi][2], af[mi][3],
                          bf[ni][0], bf[ni][1]);
        }

        // E = exp2(S^T) via fp16x2 MUFU; L += E · ones
#pragma unroll
        for (int ks2 = 0; ks2 < 4; ks2++)
#pragma unroll
            for (int mi = 0; mi < 2; mi++) {
                const float* s0 = sv[mi][2 * ks2];
                const float* s1 = sv[mi][2 * ks2 + 1];
                uint32_t a0 = ex2h2(pk(s0[0], s0[1]));
                uint32_t a1 = ex2h2(pk(s0[2], s0[3]));
                uint32_t a2 = ex2h2(pk(s1[0], s1[1]));
                uint32_t a3 = ex2h2(pk(s1[2], s1[3]));
                mma16(La[mi], a0, a1, a2, a3, ONE2, ONE2);
            }
    }

    if (tc == 0) {
#pragma unroll
        for (int mi = 0; mi < 2; mi++) {
            Lsh[wn][wm * 32 + mi * 16 + gr] = La[mi][0];
            Lsh[wn][wm * 32 + mi * 16 + gr + 8] = La[mi][2];
        }
    }
    __syncthreads();
    if (tid < 128) g_il[bh * Sc + kb + tid] = 1.f / (Lsh[0][tid] + Lsh[1][tid]);
}

// ===========================================================================
// Fused V-projection + column-softmax, PDL secondary of proj_qk:
// proj_v blocks run immediately (no dependency on Qp/Kp);
// colsum blocks gdc_wait for proj_qk completion first.
// ===========================================================================
#define FUS_SMEM (PROJ_SMEM > CS_SMEM ? PROJ_SMEM : CS_SMEM)

__global__ __launch_bounds__(256, 2) void fused_vcs(PArgs pv)
{
    extern __shared__ __half fsm[];
    gdc_launch();
    const int bid = blockIdx.x;
    if (bid < 256) {
        proj_body(pv, bid & 7, bid >> 3, fsm);     // needs only conv outputs
    } else {
        gdc_wait();                                 // needs Qp/Kp complete
        const int id = bid - 256;
        colsum_body(id >> 4, id & 15, fsm);
    }
}

// ===========================================================================
// Attention output: O = sum_k exp2(s)*il*V — fp16 exp path, il as half2.
// CTA: 128 q x one head; 8 warps x 16 q rows, full 128-k tile per warp;
// Q frags hoisted; V B-frags via ldmatrix.x4.trans. 256 thr, 2 CTAs/SM.
// PDL secondary of fused_vcs (waits for il/Vp).
// ===========================================================================
#define AOFF_K0 (128 * AST)
#define AOFF_K1 (2 * 128 * AST)
#define AOFF_V0 (3 * 128 * AST)
#define AOFF_V1 (4 * 128 * AST)
#define AOFF_IL (5 * 128 * AST)                 // uint32 ilh[2][64]
#define ATTN_SMEM (AOFF_IL * 2 + 1024)

__global__ __launch_bounds__(256, 2) void attn_mma()
{
    extern __shared__ __half asm_[];
    uint32_t* ilh = (uint32_t*)(asm_ + AOFF_IL);   // [2][64] half2-packed il

    gdc_launch();
    gdc_wait();

    const int tid = threadIdx.x;
    const int w = tid >> 5, lane = tid & 31;
    const int gr = lane >> 2, tc = lane & 3;
    const int bh = blockIdx.y, b = bh >> 4, h = bh & 15;
    const int qb = blockIdx.x * 128;
    const int l16 = lane & 15, lh = (lane >> 4) << 4;

    const uint32_t base = smem_u32(asm_);
    const uint32_t qs_b = base;
    const uint32_t ks_bb[2] = { base + AOFF_K0 * 2u, base + AOFF_K1 * 2u };
    const uint32_t vs_bb[2] = { base + AOFF_V0 * 2u, base + AOFF_V1 * 2u };

    const __half* Qbase = g_Qp + (size_t)(b * Sc + qb) * Dc + h * DHc;
    const __half* Kbase = g_Kp + (size_t)(b * Sc) * Dc + h * DHc;
    const __half* Vbase = g_Vp + (size_t)(b * Sc) * Dc + h * DHc;

#pragma unroll
    for (int i = 0; i < 4; i++) {
        int slot = tid + i * 256, row = slot >> 3, ch = slot & 7;
        cpa16(qs_b + row * (AST * 2) + ch * 16, Qbase + (size_t)row * Dc + ch * 8);
    }
    CP_COMMIT();
#pragma unroll
    for (int i = 0; i < 4; i++) {
        int slot = tid + i * 256, row = slot >> 3, ch = slot & 7;
        uint32_t so = row * (AST * 2) + ch * 16;
        size_t go = (size_t)row * Dc + ch * 8;
        cpa16(ks_bb[0] + so, Kbase + go);
        cpa16(vs_bb[0] + so, Vbase + go);
    }
    if (tid < 64)
        ilh[tid] = pk(g_il[bh * Sc + 2 * tid], g_il[bh * Sc + 2 * tid + 1]);
    CP_COMMIT();

    cp_wait<1>();
    __syncthreads();
    uint32_t aq[4][4];
#pragma unroll
    for (int st = 0; st < 4; st++)
        ldm_x4(aq[st], qs_b + (uint32_t)(w * 16 + l16) * (AST * 2) + st * 32 + lh);

    float o[8][4];
#pragma unroll
    for (int ni = 0; ni < 8; ni++)
#pragma unroll
        for (int k = 0; k < 4; k++) o[ni][k] = 0.f;

    for (int kt = 0; kt < 16; kt++) {
        const int buf = kt & 1;
        cp_wait<0>();
        __syncthreads();
        if (kt + 1 < 16) {
            const int nb = (kt + 1) & 1;
            const __half* Kn = Kbase + (size_t)(kt + 1) * 128 * Dc;
            const __half* Vn = Vbase + (size_t)(kt + 1) * 128 * Dc;
#pragma unroll
            for (int i = 0; i < 4; i++) {
                int slot = tid + i * 256, row = slot >> 3, ch = slot & 7;
                uint32_t so = row * (AST * 2) + ch * 16;
                size_t go = (size_t)row * Dc + ch * 8;
                cpa16(ks_bb[nb] + so, Kn + go);
                cpa16(vs_bb[nb] + so, Vn + go);
            }
            if (tid < 64)
                ilh[nb * 64 + tid] = pk(g_il[bh * Sc + (kt + 1) * 128 + 2 * tid],
                                        g_il[bh * Sc + (kt + 1) * 128 + 2 * tid + 1]);
        }
        CP_COMMIT();

        const uint32_t ksb = ks_bb[buf];
        const uint32_t vsb = vs_bb[buf];
        const uint32_t* ilbh = ilh + buf * 64;

#pragma unroll
        for (int c = 0; c < 4; c++) {
            float sv[4][4];
#pragma unroll
            for (int ni = 0; ni < 4; ni++)
#pragma unroll
                for (int k = 0; k < 4; k++) sv[ni][k] = 0.f;

#pragma unroll
            for (int st = 0; st < 4; st++) {
                uint32_t bk[2][4];
#pragma unroll
                for (int j = 0; j < 2; j++)
                    ldm_x4(bk[j], ksb + (uint32_t)(c * 32 + j * 16 + l16) * (AST * 2)
                                      + st * 32 + lh);
#pragma unroll
                for (int ni = 0; ni < 4; ni++)
                    mma16(sv[ni], aq[st][0], aq[st][1], aq[st][2], aq[st][3],
                          bk[ni >> 1][(ni & 1)], bk[ni >> 1][(ni & 1) + 2]);
            }

            // P = exp2(S)*il via fp16x2 (half the MUFU ops, 3 instr/word)
#pragma unroll
            for (int ks2 = 0; ks2 < 2; ks2++) {
                const int kl2 = c * 16 + ks2 * 8;
                uint32_t il0 = ilbh[kl2 + tc];
                uint32_t il1 = ilbh[kl2 + 4 + tc];

                const float* s0 = sv[2 * ks2];
                const float* s1 = sv[2 * ks2 + 1];
                uint32_t a0 = mulh2(ex2h2(pk(s0[0], s0[1])), il0);
                uint32_t a1 = mulh2(ex2h2(pk(s0[2], s0[3])), il0);
                uint32_t a2 = mulh2(ex2h2(pk(s1[0], s1[1])), il1);
                uint32_t a3 = mulh2(ex2h2(pk(s1[2], s1[3])), il1);

#pragma unroll
                for (int ni2 = 0; ni2 < 4; ni2++) {
                    uint32_t bv[4];
                    ldm_x4t(bv, vsb + (uint32_t)(c * 32 + ks2 * 16 + l16) * (AST * 2)
                                   + (uint32_t)(ni2 * 32) + lh);
                    mma16(o[2 * ni2],     a0, a1, a2, a3, bv[0], bv[1]);
                    mma16(o[2 * ni2 + 1], a0, a1, a2, a3, bv[2], bv[3]);
                }
            }
        }
    }

    const int q0 = qb + w * 16 + gr;
#pragma unroll
    for (int ni = 0; ni < 8; ni++) {
        int dg = h * DHc + ni * 8 + 2 * tc;
        *(uint32_t*)(g_AOp + (size_t)(b * Sc + q0) * Dc + dg) = pk(o[ni][0], o[ni][1]);
        *(uint32_t*)(g_AOp + (size_t)(b * Sc + q0 + 8) * Dc + dg) = pk(o[ni][2], o[ni][3]);
    }
}

// ===========================================================================
// Host
// ===========================================================================
extern "C" void kernel_launch(void* const* d_in, const int* in_sizes, int n_in,
                              void* d_out, int out_size)
{
    (void)in_sizes; (void)n_in; (void)out_size;
    const float* query = (const float*)d_in[0];
    const float* key   = (const float*)d_in[1];
    const float* value = (const float*)d_in[2];
    const float* Wq = (const float*)d_in[3];
    const float* bq = (const float*)d_in[4];
    const float* Wk = (const float*)d_in[5];
    const float* bk = (const float*)d_in[6];
    const float* Wv = (const float*)d_in[7];
    const float* bv = (const float*)d_in[8];
    const float* Wo = (const float*)d_in[9];
    const float* bo = (const float*)d_in[10];
    float* out = (float*)d_out;

    void *qin, *kin, *vin, *wqp, *wkp, *wvp, *wop, *Qp, *Kp, *Vp, *AOp;
    cudaGetSymbolAddress(&qin, g_qin); cudaGetSymbolAddress(&kin, g_kin);
    cudaGetSymbolAddress(&vin, g_vin); cudaGetSymbolAddress(&wqp, g_wq);
    cudaGetSymbolAddress(&wkp, g_wk);  cudaGetSymbolAddress(&wvp, g_wv);
    cudaGetSymbolAddress(&wop, g_wo);  cudaGetSymbolAddress(&Qp, g_Qp);
    cudaGetSymbolAddress(&Kp, g_Kp);   cudaGetSymbolAddress(&Vp, g_Vp);
    cudaGetSymbolAddress(&AOp, g_AOp);

    cudaFuncSetAttribute(proj_mma,  cudaFuncAttributeMaxDynamicSharedMemorySize, PROJ_SMEM);
    cudaFuncSetAttribute(fused_vcs, cudaFuncAttributeMaxDynamicSharedMemorySize, FUS_SMEM);
    cudaFuncSetAttribute(attn_mma,  cudaFuncAttributeMaxDynamicSharedMemorySize, ATTN_SMEM);

    const int n8big = BSc * Dc / 8, n8w = Dc * Dc / 8;
    conv_all<<<n8big / 256, 256>>>(query, key, value, Wq, Wk, Wv, Wo,
        (__half*)qin, (__half*)kin, (__half*)vin,
        (__half*)wqp, (__half*)wkp, (__half*)wvp, (__half*)wop, n8big, n8w);

    PArgs pq = { (__half*)qin, (__half*)wqp, bq, (__half*)Qp, nullptr, 0.125f * 1.44269504f };
    PArgs pkx = { (__half*)kin, (__half*)wkp, bk, (__half*)Kp, nullptr, 1.f };
    PArgs pv = { (__half*)vin, (__half*)wvp, bv, (__half*)Vp, nullptr, 1.f };
    PArgs po = { (__half*)AOp, (__half*)wop, bo, nullptr, out, 1.f };

    dim3 gqk(Dc / 128, BSc / 128, 2);    // (8, 32, 2): Q and K projections
    dim3 gproj(Dc / 128, BSc / 128, 1);  // (8, 32): O projection
    dim3 gattn(Sc / 128, BHc);           // (16, 32)

    // proj_qk: plain launch (deps on conv via normal stream order)
    proj_mma<<<gqk, 256, PROJ_SMEM>>>(pq, pkx, pkx);

    // fused_vcs: PDL secondary — proj_v half overlaps proj_qk tail
    {
        cudaLaunchConfig_t cfg = {};
        cfg.gridDim = dim3(768, 1, 1); cfg.blockDim = dim3(256, 1, 1);
        cfg.dynamicSmemBytes = FUS_SMEM;
        cudaLaunchAttribute at[1];
        at[0].id = cudaLaunchAttributeProgrammaticStreamSerialization;
        at[0].val.programmaticStreamSerializationAllowed = 1;
        cfg.attrs = at; cfg.numAttrs = 1;
        cudaLaunchKernelEx(&cfg, fused_vcs, pv);
    }
    // attn: PDL secondary of fused_vcs (waits at entry)
    {
        cudaLaunchConfig_t cfg = {};
        cfg.gridDim = gattn; cfg.blockDim = dim3(256, 1, 1);
        cfg.dynamicSmemBytes = ATTN_SMEM;
        cudaLaunchAttribute at[1];
        at[0].id = cudaLaunchAttributeProgrammaticStreamSerialization;
        at[0].val.programmaticStreamSerializationAllowed = 1;
        cfg.attrs = at; cfg.numAttrs = 1;
        cudaLaunchKernelEx(&cfg, attn_mma);
    }
    // proj_o: PDL secondary of attn (waits at entry)
    {
        cudaLaunchConfig_t cfg = {};
        cfg.gridDim = gproj; cfg.blockDim = dim3(256, 1, 1);
        cfg.dynamicSmemBytes = PROJ_SMEM;
        cudaLaunchAttribute at[1];
        at[0].id = cudaLaunchAttributeProgrammaticStreamSerialization;
        at[0].val.programmaticStreamSerializationAllowed = 1;
        cfg.attrs = at; cfg.numAttrs = 1;
        cudaLaunchKernelEx(&cfg, proj_mma, po, po, po);
    }
}

// round 17
// speedup vs baseline: 1.1890x; 1.0153x over previous
#include <cuda_runtime.h>
#include <cuda_fp16.h>
#include <cstdint>

#define Bc 2
#define Sc 2048
#define Dc 1024
#define Hc 16
#define DHc 64
#define BSc (Bc*Sc)
#define BHc (Bc*Hc)

// fp16 scratch (allocation-free rule): __device__ globals
__device__ __align__(16) __half g_qin[BSc*Dc];
__device__ __align__(16) __half g_kin[BSc*Dc];
__device__ __align__(16) __half g_vin[BSc*Dc];
__device__ __align__(16) __half g_wq[Dc*Dc];
__device__ __align__(16) __half g_wk[Dc*Dc];
__device__ __align__(16) __half g_wv[Dc*Dc];
__device__ __align__(16) __half g_wo[Dc*Dc];
__device__ __align__(16) __half g_Qp[BSc*Dc];   // pre-scaled by log2e/8
__device__ __align__(16) __half g_Kp[BSc*Dc];
__device__ __align__(16) __half g_Vp[BSc*Dc];
__device__ __align__(16) __half g_AOp[BSc*Dc];
__device__ float g_il[BHc*Sc];

// ---------------------------------------------------------------------------
// Primitives (sm_75+/sm_80+/sm_90 baseline ISA — family-portable)
// ---------------------------------------------------------------------------
__device__ __forceinline__ uint32_t smem_u32(const void* p) {
    uint32_t a;
    asm("{ .reg .u64 t; cvta.to.shared.u64 t, %1; cvt.u32.u64 %0, t; }"
        : "=r"(a) : "l"(p));
    return a;
}
__device__ __forceinline__ uint32_t pk(float x, float y) {
    __half2 h = __floats2half2_rn(x, y);
    return *(uint32_t*)&h;
}
__device__ __forceinline__ uint32_t ex2h2(uint32_t h2) {
    uint32_t r;
    asm("ex2.approx.f16x2 %0, %1;" : "=r"(r) : "r"(h2));
    return r;
}
__device__ __forceinline__ uint32_t mulh2(uint32_t a, uint32_t b) {
    uint32_t r;
    asm("mul.rn.f16x2 %0, %1, %2;" : "=r"(r) : "r"(a), "r"(b));
    return r;
}
// PDL controls (baseline sm_90 PTX, family-portable)
__device__ __forceinline__ void gdc_launch() {
    asm volatile("griddepcontrol.launch_dependents;" ::: "memory");
}
__device__ __forceinline__ void gdc_wait() {
    asm volatile("griddepcontrol.wait;" ::: "memory");
}
__device__ __forceinline__ void cpa16(uint32_t s, const void* g) {
    asm volatile("cp.async.cg.shared.global [%0], [%1], 16;" :: "r"(s), "l"(g) : "memory");
}
#define CP_COMMIT() asm volatile("cp.async.commit_group;" ::: "memory")
template<int N> __device__ __forceinline__ void cp_wait() {
    asm volatile("cp.async.wait_group %0;" :: "n"(N) : "memory");
}
__device__ __forceinline__ void ldm_x4(uint32_t* r, uint32_t addr) {
    asm volatile("ldmatrix.sync.aligned.m8n8.x4.shared.b16 {%0,%1,%2,%3}, [%4];"
        : "=r"(r[0]), "=r"(r[1]), "=r"(r[2]), "=r"(r[3]) : "r"(addr));
}
__device__ __forceinline__ void ldm_x4t(uint32_t* r, uint32_t addr) {
    asm volatile("ldmatrix.sync.aligned.m8n8.x4.trans.shared.b16 {%0,%1,%2,%3}, [%4];"
        : "=r"(r[0]), "=r"(r[1]), "=r"(r[2]), "=r"(r[3]) : "r"(addr));
}
__device__ __forceinline__ void mma16(float* c,
    uint32_t a0, uint32_t a1, uint32_t a2, uint32_t a3, uint32_t b0, uint32_t b1)
{
    asm("mma.sync.aligned.m16n8k16.row.col.f32.f16.f16.f32 "
        "{%0,%1,%2,%3},{%4,%5,%6,%7},{%8,%9},{%0,%1,%2,%3};"
        : "+f"(c[0]), "+f"(c[1]), "+f"(c[2]), "+f"(c[3])
        : "r"(a0), "r"(a1), "r"(a2), "r"(a3), "r"(b0), "r"(b1));
}
#define ONE2 0x3C003C00u   // fp16x2 {1.0, 1.0}

// ===========================================================================
// Fused fp32 -> fp16 converts: 3 big inputs + 4 weights, one launch
// ===========================================================================
__device__ __forceinline__ void cv8(const float* s, __half* d, size_t i) {
    const float4* sp = (const float4*)s + 2 * i;
    float4 a = sp[0], b = sp[1];
    *(uint4*)(d + 8 * i) =
        make_uint4(pk(a.x, a.y), pk(a.z, a.w), pk(b.x, b.y), pk(b.z, b.w));
}
__global__ __launch_bounds__(256) void conv_all(
    const float* __restrict__ s0, const float* __restrict__ s1,
    const float* __restrict__ s2, const float* __restrict__ w0,
    const float* __restrict__ w1, const float* __restrict__ w2,
    const float* __restrict__ w3,
    __half* __restrict__ d0, __half* __restrict__ d1, __half* __restrict__ d2,
    __half* __restrict__ e0, __half* __restrict__ e1, __half* __restrict__ e2,
    __half* __restrict__ e3, int n8big, int n8w)
{
    gdc_launch();
    size_t i = blockIdx.x * 256 + threadIdx.x;
    if (i < (size_t)n8big) { cv8(s0, d0, i); cv8(s1, d1, i); cv8(s2, d2, i); }
    if (i < (size_t)n8w) { cv8(w0, e0, i); cv8(w1, e1, i); cv8(w2, e2, i); cv8(w3, e3, i); }
}

// ===========================================================================
// Projection GEMM body: C[m,n] = (sum_k A[m,k]W[n,k] + b)*osc
// CTA 128x128, 8 warps (2m x 4n), BK=32, 3-stage cp.async ring.
// ===========================================================================
#define PST 40
#define PROJ_SMEM (6 * 128 * PST * 2)   // 61440 bytes

struct PArgs {
    const __half* A; const __half* W; const float* bias;
    __half* Ch; float* Cf; float osc;
};

__device__ __forceinline__ void proj_issue(
    uint32_t as_b, uint32_t ws_b, const __half* A, const __half* W, int tid, int k0)
{
#pragma unroll
    for (int i = 0; i < 2; i++) {
        int slot = tid + i * 256, row = slot >> 2, ch = slot & 3;
        cpa16(as_b + row * (PST * 2) + ch * 16, A + (size_t)row * Dc + k0 + ch * 8);
        cpa16(ws_b + row * (PST * 2) + ch * 16, W + (size_t)row * Dc + k0 + ch * 8);
    }
}

__device__ void proj_body(const PArgs& p, int bx, int by, __half* psm)
{
    __shared__ float bias_sh[128];

    const int tid = threadIdx.x;
    const int w = tid >> 5, lane = tid & 31;
    const int gr = lane >> 2, tc = lane & 3;
    const int wm = w >> 2, wn = w & 3;
    const int br = by * 128, bc = bx * 128;
    const int l16 = lane & 15, lh = (lane >> 4) << 4;

    const __half* Ab = p.A + (size_t)br * Dc;
    const __half* Wb = p.W + (size_t)bc * Dc;
    const uint32_t base = smem_u32(psm);
    if (tid < 128) bias_sh[tid] = p.bias[bc + tid];

    float acc[4][4][4];
#pragma unroll
    for (int i = 0; i < 4; i++)
#pragma unroll
        for (int j = 0; j < 4; j++)
#pragma unroll
            for (int k = 0; k < 4; k++) acc[i][j][k] = 0.f;

    proj_issue(base, base + 30720u, Ab, Wb, tid, 0);  CP_COMMIT();
    proj_issue(base + 10240u, base + 40960u, Ab, Wb, tid, 32);  CP_COMMIT();

    for (int it = 0; it < 32; it++) {
        cp_wait<1>();
        __syncthreads();
        if (it + 2 < 32) {
            int s = (it + 2) % 3;
            proj_issue(base + (uint32_t)s * 10240u, base + 30720u + (uint32_t)s * 10240u,
                       Ab, Wb, tid, (it + 2) * 32);
        }
        CP_COMMIT();

        const int s = it % 3;
        const uint32_t as_b = base + (uint32_t)s * 10240u;
        const __half* Ws_s = psm + 15360 + s * 5120;
#pragma unroll
        for (int kk = 0; kk < 2; kk++) {
            uint32_t af[4][4], bf[4][2];
#pragma unroll
            for (int mi = 0; mi < 4; mi++)
                ldm_x4(af[mi], as_b + (uint32_t)(wm * 64 + mi * 16 + l16) * (PST * 2)
                                    + kk * 32 + lh);
#pragma unroll
            for (int ni = 0; ni < 4; ni++) {
                int hidx = (wn * 32 + ni * 8 + gr) * PST + kk * 16 + 2 * tc;
                bf[ni][0] = *(const uint32_t*)&Ws_s[hidx];
                bf[ni][1] = *(const uint32_t*)&Ws_s[hidx + 8];
            }
#pragma unroll
            for (int mi = 0; mi < 4; mi++)
#pragma unroll
                for (int ni = 0; ni < 4; ni++)
                    mma16(acc[mi][ni], af[mi][0], af[mi][1], af[mi][2], af[mi][3],
                          bf[ni][0], bf[ni][1]);
        }
    }

#pragma unroll
    for (int mi = 0; mi < 4; mi++) {
        int m0 = br + wm * 64 + mi * 16 + gr;
#pragma unroll
        for (int ni = 0; ni < 4; ni++) {
            int n = wn * 32 + ni * 8 + 2 * tc;
            float v00 = (acc[mi][ni][0] + bias_sh[n]) * p.osc;
            float v01 = (acc[mi][ni][1] + bias_sh[n + 1]) * p.osc;
            float v10 = (acc[mi][ni][2] + bias_sh[n]) * p.osc;
            float v11 = (acc[mi][ni][3] + bias_sh[n + 1]) * p.osc;
            if (p.Cf) {
                *(float2*)(p.Cf + (size_t)m0 * Dc + bc + n) = make_float2(v00, v01);
                *(float2*)(p.Cf + (size_t)(m0 + 8) * Dc + bc + n) = make_float2(v10, v11);
            } else {
                *(uint32_t*)(p.Ch + (size_t)m0 * Dc + bc + n) = pk(v00, v01);
                *(uint32_t*)(p.Ch + (size_t)(m0 + 8) * Dc + bc + n) = pk(v10, v11);
            }
        }
    }
}

// QK projections (primary of fused_vcs); also O projection (PDL secondary).
__global__ __launch_bounds__(256, 2) void proj_mma(PArgs p0, PArgs p1, PArgs p2)
{
    extern __shared__ __half psm[];
    gdc_launch();
    gdc_wait();
    const PArgs p = (blockIdx.z == 0) ? p0 : (blockIdx.z == 1) ? p1 : p2;
    proj_body(p, blockIdx.x, blockIdx.y, psm);
}

// ===========================================================================
// Column softmax body: il[bh,k] = 1/sum_q exp2(Qs·K)
// S^T = K·Q^T; fp16 exp2 frags reduced over q with ones-MMA.
// K fragments hoisted to registers (loop-invariant); ni in 2 halves of 4
// to fit the register budget. La accumulation order preserved.
// ===========================================================================
#define AST 72
#define CS_SMEM (3 * 128 * AST * 2)   // 55296 bytes

__device__ void colsum_body(int bh, int kb4, __half* csm)
{
    __shared__ float Lsh[2][128];

    const int tid = threadIdx.x;
    const int w = tid >> 5, lane = tid & 31;
    const int gr = lane >> 2, tc = lane & 3;
    const int wm = w >> 1, wn = w & 1;
    const int b = bh >> 4, h = bh & 15;
    const int kb = kb4 * 128;
    const int l16 = lane & 15, lh = (lane >> 4) << 4;

    const uint32_t ks_b = smem_u32(csm);
    const uint32_t qs_bb[2] = { ks_b + 128u * AST * 2u, ks_b + 2u * 128u * AST * 2u };

    const __half* Kbase = g_Kp + (size_t)(b * Sc + kb) * Dc + h * DHc;
    const __half* Qbase = g_Qp + (size_t)(b * Sc) * Dc + h * DHc;

#pragma unroll
    for (int i = 0; i < 4; i++) {
        int slot = tid + i * 256, row = slot >> 3, ch = slot & 7;
        cpa16(ks_b + row * (AST * 2) + ch * 16, Kbase + (size_t)row * Dc + ch * 8);
        cpa16(qs_bb[0] + row * (AST * 2) + ch * 16, Qbase + (size_t)row * Dc + ch * 8);
    }
    CP_COMMIT();

    float La[2][4];
#pragma unroll
    for (int mi = 0; mi < 2; mi++)
#pragma unroll
        for (int k = 0; k < 4; k++) La[mi][k] = 0.f;

    uint32_t afr[2][4][4];   // hoisted K fragments [mi][st][frag]

    for (int qt = 0; qt < 16; qt++) {
        cp_wait<0>();
        __syncthreads();
        if (qt + 1 < 16) {
            const __half* Qn = Qbase + (size_t)(qt + 1) * 128 * Dc;
            const uint32_t dstb = qs_bb[(qt + 1) & 1];
#pragma unroll
            for (int i = 0; i < 4; i++) {
                int slot = tid + i * 256, row = slot >> 3, ch = slot & 7;
                cpa16(dstb + row * (AST * 2) + ch * 16, Qn + (size_t)row * Dc + ch * 8);
            }
        }
        CP_COMMIT();

        if (qt == 0) {
#pragma unroll
            for (int mi = 0; mi < 2; mi++)
#pragma unroll
                for (int st = 0; st < 4; st++)
                    ldm_x4(afr[mi][st],
                           ks_b + (uint32_t)(wm * 32 + mi * 16 + l16) * (AST * 2)
                                + st * 32 + lh);
        }

        const __half* Qs = (const __half*)(csm + (qt & 1 ? 2 : 1) * 128 * AST);

#pragma unroll
        for (int half = 0; half < 2; half++) {
            float sv[2][4][4];
#pragma unroll
            for (int mi = 0; mi < 2; mi++)
#pragma unroll
                for (int n4 = 0; n4 < 4; n4++)
#pragma unroll
                    for (int k = 0; k < 4; k++) sv[mi][n4][k] = 0.f;

#pragma unroll
            for (int st = 0; st < 4; st++) {
                uint32_t bf[4][2];
#pragma unroll
                for (int n4 = 0; n4 < 4; n4++) {
                    int hidx = (wn * 64 + (half * 4 + n4) * 8 + gr) * AST + st * 16 + 2 * tc;
                    bf[n4][0] = *(const uint32_t*)&Qs[hidx];
                    bf[n4][1] = *(const uint32_t*)&Qs[hidx + 8];
                }
#pragma unroll
                for (int mi = 0; mi < 2; mi++)
#pragma unroll
                    for (int n4 = 0; n4 < 4; n4++)
                        mma16(sv[mi][n4], afr[mi][st][0], afr[mi][st][1],
                              afr[mi][st][2], afr[mi][st][3],
                              bf[n4][0], bf[n4][1]);
            }

            // E = exp2(S^T) via fp16x2 MUFU; L += E · ones (order preserved)
#pragma unroll
            for (int p2i = 0; p2i < 2; p2i++)
#pragma unroll
                for (int mi = 0; mi < 2; mi++) {
                    const float* s0 = sv[mi][2 * p2i];
                    const float* s1 = sv[mi][2 * p2i + 1];
                    uint32_t a0 = ex2h2(pk(s0[0], s0[1]));
                    uint32_t a1 = ex2h2(pk(s0[2], s0[3]));
                    uint32_t a2 = ex2h2(pk(s1[0], s1[1]));
                    uint32_t a3 = ex2h2(pk(s1[2], s1[3]));
                    mma16(La[mi], a0, a1, a2, a3, ONE2, ONE2);
                }
        }
    }

    if (tc == 0) {
#pragma unroll
        for (int mi = 0; mi < 2; mi++) {
            Lsh[wn][wm * 32 + mi * 16 + gr] = La[mi][0];
            Lsh[wn][wm * 32 + mi * 16 + gr + 8] = La[mi][2];
        }
    }
    __syncthreads();
    if (tid < 128) g_il[bh * Sc + kb + tid] = 1.f / (Lsh[0][tid] + Lsh[1][tid]);
}

// ===========================================================================
// Fused V-projection + column-softmax, PDL secondary of proj_qk.
// ===========================================================================
#define FUS_SMEM (PROJ_SMEM > CS_SMEM ? PROJ_SMEM : CS_SMEM)

__global__ __launch_bounds__(256, 2) void fused_vcs(PArgs pv)
{
    extern __shared__ __half fsm[];
    gdc_launch();
    const int bid = blockIdx.x;
    if (bid < 256) {
        proj_body(pv, bid & 7, bid >> 3, fsm);     // needs only conv outputs
    } else {
        gdc_wait();                                 // needs Qp/Kp complete
        const int id = bid - 256;
        colsum_body(id >> 4, id & 15, fsm);
    }
}

// ===========================================================================
// Attention output: O = sum_k exp2(s)*il*V — fp16 exp path, il as half2.
// CTA: 128 q x one head; 8 warps x 16 q rows, full 128-k tile per warp;
// Q frags hoisted; V ldmatrix pipelined against the exp phase.
// PDL secondary of fused_vcs.
// ===========================================================================
#define AOFF_K0 (128 * AST)
#define AOFF_K1 (2 * 128 * AST)
#define AOFF_V0 (3 * 128 * AST)
#define AOFF_V1 (4 * 128 * AST)
#define AOFF_IL (5 * 128 * AST)                 // uint32 ilh[2][64]
#define ATTN_SMEM (AOFF_IL * 2 + 1024)

__global__ __launch_bounds__(256, 2) void attn_mma()
{
    extern __shared__ __half asm_[];
    uint32_t* ilh = (uint32_t*)(asm_ + AOFF_IL);   // [2][64] half2-packed il

    gdc_launch();
    gdc_wait();

    const int tid = threadIdx.x;
    const int w = tid >> 5, lane = tid & 31;
    const int gr = lane >> 2, tc = lane & 3;
    const int bh = blockIdx.y, b = bh >> 4, h = bh & 15;
    const int qb = blockIdx.x * 128;
    const int l16 = lane & 15, lh = (lane >> 4) << 4;

    const uint32_t base = smem_u32(asm_);
    const uint32_t qs_b = base;
    const uint32_t ks_bb[2] = { base + AOFF_K0 * 2u, base + AOFF_K1 * 2u };
    const uint32_t vs_bb[2] = { base + AOFF_V0 * 2u, base + AOFF_V1 * 2u };

    const __half* Qbase = g_Qp + (size_t)(b * Sc + qb) * Dc + h * DHc;
    const __half* Kbase = g_Kp + (size_t)(b * Sc) * Dc + h * DHc;
    const __half* Vbase = g_Vp + (size_t)(b * Sc) * Dc + h * DHc;

#pragma unroll
    for (int i = 0; i < 4; i++) {
        int slot = tid + i * 256, row = slot >> 3, ch = slot & 7;
        cpa16(qs_b + row * (AST * 2) + ch * 16, Qbase + (size_t)row * Dc + ch * 8);
    }
    CP_COMMIT();
#pragma unroll
    for (int i = 0; i < 4; i++) {
        int slot = tid + i * 256, row = slot >> 3, ch = slot & 7;
        uint32_t so = row * (AST * 2) + ch * 16;
        size_t go = (size_t)row * Dc + ch * 8;
        cpa16(ks_bb[0] + so, Kbase + go);
        cpa16(vs_bb[0] + so, Vbase + go);
    }
    if (tid < 64)
        ilh[tid] = pk(g_il[bh * Sc + 2 * tid], g_il[bh * Sc + 2 * tid + 1]);
    CP_COMMIT();

    cp_wait<1>();
    __syncthreads();
    uint32_t aq[4][4];
#pragma unroll
    for (int st = 0; st < 4; st++)
        ldm_x4(aq[st], qs_b + (uint32_t)(w * 16 + l16) * (AST * 2) + st * 32 + lh);

    float o[8][4];
#pragma unroll
    for (int ni = 0; ni < 8; ni++)
#pragma unroll
        for (int k = 0; k < 4; k++) o[ni][k] = 0.f;

    for (int kt = 0; kt < 16; kt++) {
        const int buf = kt & 1;
        cp_wait<0>();
        __syncthreads();
        if (kt + 1 < 16) {
            const int nb = (kt + 1) & 1;
            const __half* Kn = Kbase + (size_t)(kt + 1) * 128 * Dc;
            const __half* Vn = Vbase + (size_t)(kt + 1) * 128 * Dc;
#pragma unroll
            for (int i = 0; i < 4; i++) {
                int slot = tid + i * 256, row = slot >> 3, ch = slot & 7;
                uint32_t so = row * (AST * 2) + ch * 16;
                size_t go = (size_t)row * Dc + ch * 8;
                cpa16(ks_bb[nb] + so, Kn + go);
                cpa16(vs_bb[nb] + so, Vn + go);
            }
            if (tid < 64)
                ilh[nb * 64 + tid] = pk(g_il[bh * Sc + (kt + 1) * 128 + 2 * tid],
                                        g_il[bh * Sc + (kt + 1) * 128 + 2 * tid + 1]);
        }
        CP_COMMIT();

        const uint32_t ksb = ks_bb[buf];
        const uint32_t vsb = vs_bb[buf];
        const uint32_t* ilbh = ilh + buf * 64;

#pragma unroll
        for (int c = 0; c < 4; c++) {
            float sv[4][4];
#pragma unroll
            for (int ni = 0; ni < 4; ni++)
#pragma unroll
                for (int k = 0; k < 4; k++) sv[ni][k] = 0.f;

#pragma unroll
            for (int st = 0; st < 4; st++) {
                uint32_t bk[2][4];
#pragma unroll
                for (int j = 0; j < 2; j++)
                    ldm_x4(bk[j], ksb + (uint32_t)(c * 32 + j * 16 + l16) * (AST * 2)
                                      + st * 32 + lh);
#pragma unroll
                for (int ni = 0; ni < 4; ni++)
                    mma16(sv[ni], aq[st][0], aq[st][1], aq[st][2], aq[st][3],
                          bk[ni >> 1][(ni & 1)], bk[ni >> 1][(ni & 1) + 2]);
            }

            // P = exp2(S)*il; V ldmatrix pipelined against exp/pack
#pragma unroll
            for (int ks2 = 0; ks2 < 2; ks2++) {
                const int kl2 = c * 16 + ks2 * 8;
                const uint32_t vrow = vsb + (uint32_t)(c * 32 + ks2 * 16 + l16) * (AST * 2) + lh;

                uint32_t bv[4];
                ldm_x4t(bv, vrow);                    // ni2=0 load first

                uint32_t il0 = ilbh[kl2 + tc];
                uint32_t il1 = ilbh[kl2 + 4 + tc];
                const float* s0 = sv[2 * ks2];
                const float* s1 = sv[2 * ks2 + 1];
                uint32_t a0 = mulh2(ex2h2(pk(s0[0], s0[1])), il0);
                uint32_t a1 = mulh2(ex2h2(pk(s0[2], s0[3])), il0);
                uint32_t a2 = mulh2(ex2h2(pk(s1[0], s1[1])), il1);
                uint32_t a3 = mulh2(ex2h2(pk(s1[2], s1[3])), il1);

#pragma unroll
                for (int ni2 = 0; ni2 < 4; ni2++) {
                    uint32_t bvn[4];
                    if (ni2 < 3)
                        ldm_x4t(bvn, vrow + (uint32_t)((ni2 + 1) * 32));
                    mma16(o[2 * ni2],     a0, a1, a2, a3, bv[0], bv[1]);
                    mma16(o[2 * ni2 + 1], a0, a1, a2, a3, bv[2], bv[3]);
                    if (ni2 < 3) {
                        bv[0] = bvn[0]; bv[1] = bvn[1];
                        bv[2] = bvn[2]; bv[3] = bvn[3];
                    }
                }
            }
        }
    }

    const int q0 = qb + w * 16 + gr;
#pragma unroll
    for (int ni = 0; ni < 8; ni++) {
        int dg = h * DHc + ni * 8 + 2 * tc;
        *(uint32_t*)(g_AOp + (size_t)(b * Sc + q0) * Dc + dg) = pk(o[ni][0], o[ni][1]);
        *(uint32_t*)(g_AOp + (size_t)(b * Sc + q0 + 8) * Dc + dg) = pk(o[ni][2], o[ni][3]);
    }
}

// ===========================================================================
// Host
// ===========================================================================
extern "C" void kernel_launch(void* const* d_in, const int* in_sizes, int n_in,
                              void* d_out, int out_size)
{
    (void)in_sizes; (void)n_in; (void)out_size;
    const float* query = (const float*)d_in[0];
    const float* key   = (const float*)d_in[1];
    const float* value = (const float*)d_in[2];
    const float* Wq = (const float*)d_in[3];
    const float* bq = (const float*)d_in[4];
    const float* Wk = (const float*)d_in[5];
    const float* bk = (const float*)d_in[6];
    const float* Wv = (const float*)d_in[7];
    const float* bv = (const float*)d_in[8];
    const float* Wo = (const float*)d_in[9];
    const float* bo = (const float*)d_in[10];
    float* out = (float*)d_out;

    void *qin, *kin, *vin, *wqp, *wkp, *wvp, *wop, *Qp, *Kp, *Vp, *AOp;
    cudaGetSymbolAddress(&qin, g_qin); cudaGetSymbolAddress(&kin, g_kin);
    cudaGetSymbolAddress(&vin, g_vin); cudaGetSymbolAddress(&wqp, g_wq);
    cudaGetSymbolAddress(&wkp, g_wk);  cudaGetSymbolAddress(&wvp, g_wv);
    cudaGetSymbolAddress(&wop, g_wo);  cudaGetSymbolAddress(&Qp, g_Qp);
    cudaGetSymbolAddress(&Kp, g_Kp);   cudaGetSymbolAddress(&Vp, g_Vp);
    cudaGetSymbolAddress(&AOp, g_AOp);

    cudaFuncSetAttribute(proj_mma,  cudaFuncAttributeMaxDynamicSharedMemorySize, PROJ_SMEM);
    cudaFuncSetAttribute(fused_vcs, cudaFuncAttributeMaxDynamicSharedMemorySize, FUS_SMEM);
    cudaFuncSetAttribute(attn_mma,  cudaFuncAttributeMaxDynamicSharedMemorySize, ATTN_SMEM);

    const int n8big = BSc * Dc / 8, n8w = Dc * Dc / 8;
    conv_all<<<n8big / 256, 256>>>(query, key, value, Wq, Wk, Wv, Wo,
        (__half*)qin, (__half*)kin, (__half*)vin,
        (__half*)wqp, (__half*)wkp, (__half*)wvp, (__half*)wop, n8big, n8w);

    PArgs pq = { (__half*)qin, (__half*)wqp, bq, (__half*)Qp, nullptr, 0.125f * 1.44269504f };
    PArgs pkx = { (__half*)kin, (__half*)wkp, bk, (__half*)Kp, nullptr, 1.f };
    PArgs pv = { (__half*)vin, (__half*)wvp, bv, (__half*)Vp, nullptr, 1.f };
    PArgs po = { (__half*)AOp, (__half*)wop, bo, nullptr, out, 1.f };

    dim3 gqk(Dc / 128, BSc / 128, 2);    // (8, 32, 2): Q and K projections
    dim3 gproj(Dc / 128, BSc / 128, 1);  // (8, 32): O projection
    dim3 gattn(Sc / 128, BHc);           // (16, 32)

    // proj_qk: plain launch (deps on conv via normal stream order)
    proj_mma<<<gqk, 256, PROJ_SMEM>>>(pq, pkx, pkx);

    // fused_vcs: PDL secondary — proj_v half overlaps proj_qk tail
    {
        cudaLaunchConfig_t cfg = {};
        cfg.gridDim = dim3(768, 1, 1); cfg.blockDim = dim3(256, 1, 1);
        cfg.dynamicSmemBytes = FUS_SMEM;
        cudaLaunchAttribute at[1];
        at[0].id = cudaLaunchAttributeProgrammaticStreamSerialization;
        at[0].val.programmaticStreamSerializationAllowed = 1;
        cfg.attrs = at; cfg.numAttrs = 1;
        cudaLaunchKernelEx(&cfg, fused_vcs, pv);
    }
    // attn: PDL secondary of fused_vcs (waits at entry)
    {
        cudaLaunchConfig_t cfg = {};
        cfg.gridDim = gattn; cfg.blockDim = dim3(256, 1, 1);
        cfg.dynamicSmemBytes = ATTN_SMEM;
        cudaLaunchAttribute at[1];
        at[0].id = cudaLaunchAttributeProgrammaticStreamSerialization;
        at[0].val.programmaticStreamSerializationAllowed = 1;
        cfg.attrs = at; cfg.numAttrs = 1;
        cudaLaunchKernelEx(&cfg, attn_mma);
    }
    // proj_o: PDL secondary of attn (waits at entry)
    {
        cudaLaunchConfig_t cfg = {};
        cfg.gridDim = gproj; cfg.blockDim = dim3(256, 1, 1);
        cfg.dynamicSmemBytes = PROJ_SMEM;
        cudaLaunchAttribute at[1];
        at[0].id = cudaLaunchAttributeProgrammaticStreamSerialization;
        at[0].val.programmaticStreamSerializationAllowed = 1;
        cfg.attrs = at; cfg.numAttrs = 1;
        cudaLaunchKernelEx(&cfg, proj_mma, po, po, po);
    }
}